// round 14
// baseline (speedup 1.0000x reference)
#include <cuda_runtime.h>
#include <cuda_bf16.h>
#include <math.h>
#include <stdint.h>

typedef unsigned long long ull;
typedef unsigned int uint;

#define NMAX 50000
#define EMAX 1600000

// ---------------- device scratch (no allocations allowed) ----------------
__device__ float g_v[(size_t)NMAX * 64];        // v = u1 + 2*L(u2)
__device__ float g_u[(size_t)NMAX * 192];       // [u0 | u1 | u2]
__device__ float g_ha[(size_t)NMAX * 64];
__device__ float g_hb[(size_t)NMAX * 64];
__device__ uint2 g_ewp[EMAX];                   // {col, ew*dis[col]} in CSR order
__device__ float g_dis[NMAX];                   // rsqrt(deg) or 0
__device__ float g_deg[NMAX];
__device__ int   g_rowptr[NMAX + 1];
__device__ int   g_cursor[NMAX];
__device__ int   g_cnt[NMAX];
__device__ int   g_ecol[EMAX];                  // col in CSR order
__device__ int   g_eidx[EMAX];                  // original edge id in CSR order
__device__ float g_cw2[256 * 2];
__device__ float g_cb2[2];
// B fragments for mma GEMMs (uint4 = {hi_b0, hi_b1, lo_b0, lo_b1})
__device__ uint4 g_frag_cheb0[3 * 8 * 256];     // K=128, 192 cols
__device__ uint4 g_frag_cheb1[3 * 4 * 256];     // K=64
__device__ uint4 g_frag_cheb2[3 * 4 * 256];
__device__ uint4 g_frag_cheb3[3 * 4 * 256];
__device__ uint4 g_frag_cls[4 * 16 * 256];      // K=256, 256 cols

// ---------------- side stream + fork/join events (created pre-main, reused) ----------------
static cudaStream_t g_s2 = []() {
    cudaStream_t s; cudaStreamCreateWithFlags(&s, cudaStreamNonBlocking); return s;
}();
static cudaEvent_t g_evF = []() {
    cudaEvent_t e; cudaEventCreateWithFlags(&e, cudaEventDisableTiming); return e;
}();
static cudaEvent_t g_evJ = []() {
    cudaEvent_t e; cudaEventCreateWithFlags(&e, cudaEventDisableTiming); return e;
}();

// =================== warp-level bf16 MMA ===================
__device__ __forceinline__ void mma16816(float* d,
                                         uint a0, uint a1, uint a2, uint a3,
                                         uint b0, uint b1) {
    asm volatile(
        "mma.sync.aligned.m16n8k16.row.col.f32.bf16.bf16.f32 "
        "{%0,%1,%2,%3}, {%4,%5,%6,%7}, {%8,%9}, {%0,%1,%2,%3};"
        : "+f"(d[0]), "+f"(d[1]), "+f"(d[2]), "+f"(d[3])
        : "r"(a0), "r"(a1), "r"(a2), "r"(a3), "r"(b0), "r"(b1));
}

__device__ __forceinline__ void mma16816s(float& d0, float& d1, float& d2, float& d3,
                                          uint a0, uint a1, uint a2, uint a3,
                                          uint b0, uint b1) {
    asm volatile(
        "mma.sync.aligned.m16n8k16.row.col.f32.bf16.bf16.f32 "
        "{%0,%1,%2,%3}, {%4,%5,%6,%7}, {%8,%9}, {%0,%1,%2,%3};"
        : "+f"(d0), "+f"(d1), "+f"(d2), "+f"(d3)
        : "r"(a0), "r"(a1), "r"(a2), "r"(a3), "r"(b0), "r"(b1));
}

__device__ __forceinline__ void mma16808(float* d, uint a0, uint a1, uint b0) {
    asm volatile(
        "mma.sync.aligned.m16n8k8.row.col.f32.bf16.bf16.f32 "
        "{%0,%1,%2,%3}, {%4,%5}, {%6}, {%0,%1,%2,%3};"
        : "+f"(d[0]), "+f"(d[1]), "+f"(d[2]), "+f"(d[3])
        : "r"(a0), "r"(a1), "r"(b0));
}

__device__ __forceinline__ void split2(float a, float b, uint& hi, uint& lo) {
    __nv_bfloat162 h = __floats2bfloat162_rn(a, b);
    float2 f = __bfloat1622float2(h);
    __nv_bfloat162 l = __floats2bfloat162_rn(a - f.x, b - f.y);
    hi = *(uint*)&h;
    lo = *(uint*)&l;
}

// =================== BN folding kernel (classifier) ===================
__global__ void fold_cls_kernel(const float* __restrict__ g, const float* __restrict__ b,
                                const float* __restrict__ rm, const float* __restrict__ rv,
                                const float* __restrict__ w2, const float* __restrict__ b2,
                                float* __restrict__ cw2, float* __restrict__ cb2) {
    __shared__ float p0[256], p1[256];
    int i = threadIdx.x;  // 256 threads
    float si = g[i] * rsqrtf(rv[i] + 1e-5f);
    float ti = b[i] - rm[i] * si;
    float w0 = w2[2 * i], w1 = w2[2 * i + 1];
    cw2[2 * i]     = si * w0;
    cw2[2 * i + 1] = si * w1;
    p0[i] = ti * w0;
    p1[i] = ti * w1;
    __syncthreads();
    for (int off = 128; off; off >>= 1) {
        if (i < off) { p0[i] += p0[i + off]; p1[i] += p1[i + off]; }
        __syncthreads();
    }
    if (i == 0) { cb2[0] = b2[0] + p0[0]; cb2[1] = b2[1] + p1[0]; }
}

__global__ void logit_init_kernel(const float* __restrict__ cb2, float* __restrict__ logit, int N) {
    int i = blockIdx.x * blockDim.x + threadIdx.x;
    if (i < N) {
        logit[2 * i]     = cb2[0];
        logit[2 * i + 1] = cb2[1];
    }
}

// =================== fragment prep kernels ===================
__global__ void prep_frag(const float* __restrict__ W, int K, int Ncols, uint4* __restrict__ out) {
    int ktiles = K >> 4;
    int total = (Ncols >> 6) * ktiles * 256;
    int idx = blockIdx.x * 256 + threadIdx.x;
    if (idx >= total) return;
    int lane = idx & 31;
    int nt = (idx >> 5) & 7;
    int rest = idx >> 8;
    int kt = rest % ktiles;
    int chunk = rest / ktiles;
    int n = chunk * 64 + nt * 8 + (lane >> 2);
    int k0 = kt * 16 + (lane & 3) * 2;
    float w00 = W[(size_t)k0 * Ncols + n];
    float w01 = W[(size_t)(k0 + 1) * Ncols + n];
    float w10 = W[(size_t)(k0 + 8) * Ncols + n];
    float w11 = W[(size_t)(k0 + 9) * Ncols + n];
    uint4 v;
    split2(w00, w01, v.x, v.z);
    split2(w10, w11, v.y, v.w);
    out[idx] = v;
}

// Cheb composite Wc[k][n]: n<64: W0-W2 ; 64<=n<128: W1 ; n>=128: W2.  W: [3][K][64]
__device__ __forceinline__ void cheb_frag_body(const float* __restrict__ W, int K,
                                               uint4* __restrict__ out, int idx) {
    int ktiles = K >> 4;
    int lane = idx & 31;
    int nt = (idx >> 5) & 7;
    int rest = idx >> 8;
    int kt = rest % ktiles;
    int chunk = rest / ktiles;
    int n = chunk * 64 + nt * 8 + (lane >> 2);
    int k0 = kt * 16 + (lane & 3) * 2;
    int part = n >> 6, nn = n & 63;
    float w[4];
#pragma unroll
    for (int q = 0; q < 4; q++) {
        int k = k0 + (q >> 1) * 8 + (q & 1);
        float v;
        if (part == 0)      v = W[(size_t)k * 64 + nn] - W[(size_t)(2 * K + k) * 64 + nn];
        else if (part == 1) v = W[(size_t)(K + k) * 64 + nn];
        else                v = W[(size_t)(2 * K + k) * 64 + nn];
        w[q] = v;
    }
    uint4 v;
    split2(w[0], w[1], v.x, v.z);
    split2(w[2], w[3], v.y, v.w);
    out[idx] = v;
}

__global__ void prep_cheb_frag128(const float* __restrict__ W, uint4* __restrict__ out) {
    int idx = blockIdx.x * 256 + threadIdx.x;
    if (idx < 3 * 8 * 256) cheb_frag_body(W, 128, out, idx);
}

__global__ void prep_cheb_frag64x3(const float* __restrict__ W1, const float* __restrict__ W2,
                                   const float* __restrict__ W3,
                                   uint4* __restrict__ o1, uint4* __restrict__ o2,
                                   uint4* __restrict__ o3) {
    int idx = blockIdx.x * 256 + threadIdx.x;
    if (idx >= 3 * 4 * 256) return;
    const float* W = (blockIdx.y == 0) ? W1 : (blockIdx.y == 1) ? W2 : W3;
    uint4* out = (blockIdx.y == 0) ? o1 : (blockIdx.y == 1) ? o2 : o3;
    cheb_frag_body(W, 64, out, idx);
}

// =================== generic split-bf16 mma GEMM (per-chunk; layer 0) ===================
__global__ __launch_bounds__(256)
void gemm_mma(const float* __restrict__ A, int lda, int M,
              const uint4* __restrict__ bfrag, int ktiles,
              int ldc, float* __restrict__ C) {
    extern __shared__ uint4 sB[];   // [ktiles][8][32]
    int tid = threadIdx.x, lane = tid & 31, wid = tid >> 5;
    const uint4* src = bfrag + (size_t)blockIdx.y * ktiles * 256;
    for (int i = tid; i < ktiles * 256; i += 256) sB[i] = src[i];
    __syncthreads();

    int r1 = blockIdx.x * 128 + wid * 16 + (lane >> 2);
    int r2 = r1 + 8;
    int rl1 = min(r1, M - 1), rl2 = min(r2, M - 1);
    int cq = (lane & 3) * 2;
    const float* A1 = A + (size_t)rl1 * lda;
    const float* A2 = A + (size_t)rl2 * lda;

    float acc[8][4];
#pragma unroll
    for (int i = 0; i < 8; i++) { acc[i][0] = acc[i][1] = acc[i][2] = acc[i][3] = 0.f; }

    for (int kt = 0; kt < ktiles; kt++) {
        int k0 = kt * 16 + cq;
        float2 xa = *(const float2*)(A1 + k0);
        float2 xb = *(const float2*)(A2 + k0);
        float2 xc = *(const float2*)(A1 + k0 + 8);
        float2 xd = *(const float2*)(A2 + k0 + 8);
        uint ahi[4], alo[4];
        split2(xa.x, xa.y, ahi[0], alo[0]);
        split2(xb.x, xb.y, ahi[1], alo[1]);
        split2(xc.x, xc.y, ahi[2], alo[2]);
        split2(xd.x, xd.y, ahi[3], alo[3]);

        const uint4* bp = sB + kt * 256 + lane;
        uint4 b[8];
#pragma unroll
        for (int nt = 0; nt < 8; nt++) b[nt] = bp[nt * 32];
#pragma unroll
        for (int nt = 0; nt < 8; nt++)
            mma16816(acc[nt], ahi[0], ahi[1], ahi[2], ahi[3], b[nt].x, b[nt].y);
#pragma unroll
        for (int nt = 0; nt < 8; nt++)
            mma16816(acc[nt], alo[0], alo[1], alo[2], alo[3], b[nt].x, b[nt].y);
#pragma unroll
        for (int nt = 0; nt < 8; nt++)
            mma16816(acc[nt], ahi[0], ahi[1], ahi[2], ahi[3], b[nt].z, b[nt].w);
    }

#pragma unroll
    for (int nt = 0; nt < 8; nt++) {
        int cc = blockIdx.y * 64 + nt * 8 + cq;
        if (r1 < M) { float2 o = {acc[nt][0], acc[nt][1]}; *(float2*)(C + (size_t)r1 * ldc + cc) = o; }
        if (r2 < M) { float2 o = {acc[nt][2], acc[nt][3]}; *(float2*)(C + (size_t)r2 * ldc + cc) = o; }
    }
}

// =================== merged 3-chunk GEMM for K=64 layers ===================
__global__ __launch_bounds__(256)
void gemm_mma3(const float* __restrict__ A, int M,
               const uint4* __restrict__ bfrag, float* __restrict__ C) {
    extern __shared__ uint4 sB[];   // [3][4][8][32] = 48KB
    int tid = threadIdx.x, lane = tid & 31, wid = tid >> 5;
    for (int i = tid; i < 3 * 4 * 256; i += 256) sB[i] = bfrag[i];
    __syncthreads();

    int r1 = blockIdx.x * 128 + wid * 16 + (lane >> 2);
    int r2 = r1 + 8;
    int rl1 = min(r1, M - 1), rl2 = min(r2, M - 1);
    int cq = (lane & 3) * 2;
    const float* A1 = A + (size_t)rl1 * 64;
    const float* A2 = A + (size_t)rl2 * 64;

    float acc[24][4];
#pragma unroll
    for (int i = 0; i < 24; i++) { acc[i][0] = acc[i][1] = acc[i][2] = acc[i][3] = 0.f; }

#pragma unroll
    for (int kt = 0; kt < 4; kt++) {
        int k0 = kt * 16 + cq;
        float2 xa = *(const float2*)(A1 + k0);
        float2 xb = *(const float2*)(A2 + k0);
        float2 xc = *(const float2*)(A1 + k0 + 8);
        float2 xd = *(const float2*)(A2 + k0 + 8);
        uint ahi[4], alo[4];
        split2(xa.x, xa.y, ahi[0], alo[0]);
        split2(xb.x, xb.y, ahi[1], alo[1]);
        split2(xc.x, xc.y, ahi[2], alo[2]);
        split2(xd.x, xd.y, ahi[3], alo[3]);

#pragma unroll
        for (int c = 0; c < 3; c++) {
            const uint4* bp = sB + (c * 4 + kt) * 256 + lane;
#pragma unroll
            for (int nt = 0; nt < 8; nt++) {
                uint4 b = bp[nt * 32];
                float* d = acc[c * 8 + nt];
                mma16816(d, ahi[0], ahi[1], ahi[2], ahi[3], b.x, b.y);
                mma16816(d, alo[0], alo[1], alo[2], alo[3], b.x, b.y);
                mma16816(d, ahi[0], ahi[1], ahi[2], ahi[3], b.z, b.w);
            }
        }
    }

#pragma unroll
    for (int c = 0; c < 3; c++) {
#pragma unroll
        for (int nt = 0; nt < 8; nt++) {
            int cc = c * 64 + nt * 8 + cq;
            const float* d = acc[c * 8 + nt];
            if (r1 < M) { float2 o = {d[0], d[1]}; *(float2*)(C + (size_t)r1 * 192 + cc) = o; }
            if (r2 < M) { float2 o = {d[2], d[3]}; *(float2*)(C + (size_t)r2 * 192 + cc) = o; }
        }
    }
}

// =================== classifier GEMM fused with logit ===================
__global__ __launch_bounds__(256)
void gemm_mma_cls(const float* __restrict__ A, int lda, int M,
                  const uint4* __restrict__ bfrag, int ktiles,
                  const float* __restrict__ bias, const float* __restrict__ cw2,
                  float* __restrict__ logit) {
    extern __shared__ uint4 sB[];
    int tid = threadIdx.x, lane = tid & 31, wid = tid >> 5;
    const uint4* src = bfrag + (size_t)blockIdx.y * ktiles * 256;
    for (int i = tid; i < ktiles * 256; i += 256) sB[i] = src[i];
    __syncthreads();

    int r1 = blockIdx.x * 128 + wid * 16 + (lane >> 2);
    int r2 = r1 + 8;
    int rl1 = min(r1, M - 1), rl2 = min(r2, M - 1);
    int cq = (lane & 3) * 2;
    const float* A1 = A + (size_t)rl1 * lda;
    const float* A2 = A + (size_t)rl2 * lda;

    float acc[8][4];
#pragma unroll
    for (int i = 0; i < 8; i++) { acc[i][0] = acc[i][1] = acc[i][2] = acc[i][3] = 0.f; }

    for (int kt = 0; kt < ktiles; kt++) {
        int k0 = kt * 16 + cq;
        float2 xa = *(const float2*)(A1 + k0);
        float2 xb = *(const float2*)(A2 + k0);
        float2 xc = *(const float2*)(A1 + k0 + 8);
        float2 xd = *(const float2*)(A2 + k0 + 8);
        uint ahi[4], alo[4];
        split2(xa.x, xa.y, ahi[0], alo[0]);
        split2(xb.x, xb.y, ahi[1], alo[1]);
        split2(xc.x, xc.y, ahi[2], alo[2]);
        split2(xd.x, xd.y, ahi[3], alo[3]);

        const uint4* bp = sB + kt * 256 + lane;
        uint4 b[8];
#pragma unroll
        for (int nt = 0; nt < 8; nt++) b[nt] = bp[nt * 32];
#pragma unroll
        for (int nt = 0; nt < 8; nt++)
            mma16816(acc[nt], ahi[0], ahi[1], ahi[2], ahi[3], b[nt].x, b[nt].y);
#pragma unroll
        for (int nt = 0; nt < 8; nt++)
            mma16816(acc[nt], alo[0], alo[1], alo[2], alo[3], b[nt].x, b[nt].y);
#pragma unroll
        for (int nt = 0; nt < 8; nt++)
            mma16816(acc[nt], ahi[0], ahi[1], ahi[2], ahi[3], b[nt].z, b[nt].w);
    }

    float l0a = 0.f, l1a = 0.f, l0b = 0.f, l1b = 0.f;
#pragma unroll
    for (int nt = 0; nt < 8; nt++) {
        int cc = blockIdx.y * 64 + nt * 8 + cq;
        float b0 = bias[cc], b1 = bias[cc + 1];
        float v0 = fmaxf(acc[nt][0] + b0, 0.f);
        float v1 = fmaxf(acc[nt][1] + b1, 0.f);
        float v2 = fmaxf(acc[nt][2] + b0, 0.f);
        float v3 = fmaxf(acc[nt][3] + b1, 0.f);
        float c00 = cw2[2 * cc], c01 = cw2[2 * cc + 1];
        float c10 = cw2[2 * cc + 2], c11 = cw2[2 * cc + 3];
        l0a = fmaf(v0, c00, fmaf(v1, c10, l0a));
        l1a = fmaf(v0, c01, fmaf(v1, c11, l1a));
        l0b = fmaf(v2, c00, fmaf(v3, c10, l0b));
        l1b = fmaf(v2, c01, fmaf(v3, c11, l1b));
    }
#pragma unroll
    for (int off = 1; off <= 2; off <<= 1) {
        l0a += __shfl_xor_sync(0xffffffffu, l0a, off);
        l1a += __shfl_xor_sync(0xffffffffu, l1a, off);
        l0b += __shfl_xor_sync(0xffffffffu, l0b, off);
        l1b += __shfl_xor_sync(0xffffffffu, l1b, off);
    }
    if ((lane & 3) == 0) {
        if (r1 < M) {
            atomicAdd(&logit[2 * r1], l0a);
            atomicAdd(&logit[2 * r1 + 1], l1a);
        }
        if (r2 < M) {
            atomicAdd(&logit[2 * r2], l0b);
            atomicAdd(&logit[2 * r2 + 1], l1b);
        }
    }
}

// =================== PAE mma.sync kernel (BN fold inlined into staging; deg fused) ===================
// SMEM: [0,65536) W2fT fragments; [65536,69632) W1 k8 frags; [69632,70144) b2f;
//       [70144,70656) s scale; [70656,71168) t shift.
#define PAE_SMEM 71168

__global__ __launch_bounds__(256, 1)
void pae_mma_kernel(const float* __restrict__ edgenet,
                    const float* __restrict__ w1, const float* __restrict__ b1,
                    const float* __restrict__ bn_g, const float* __restrict__ bn_b,
                    const float* __restrict__ bn_rm, const float* __restrict__ bn_rv,
                    const float* __restrict__ w2, const float* __restrict__ b2,
                    const int* __restrict__ rowidx,
                    float* __restrict__ ew, float* __restrict__ deg, int E) {
    extern __shared__ char smraw[];
    uint4* s_bfrag = (uint4*)smraw;
    uint2* s_w1f = (uint2*)(smraw + 65536);   // [16 ntiles][32 lanes]
    float* s_b2f = (float*)(smraw + 69632);
    float* s_s   = (float*)(smraw + 70144);
    float* s_t   = (float*)(smraw + 70656);

    int tid = threadIdx.x, lane = tid & 31, wid = tid >> 5;

    // ---- BN fold scale/shift ----
    if (tid < 128) {
        float sj = __ldg(bn_g + tid) * rsqrtf(__ldg(bn_rv + tid) + 1e-5f);
        s_s[tid] = sj;
        s_t[tid] = __ldg(bn_b + tid) - __ldg(bn_rm + tid) * sj;
    }
    for (int idx = tid; idx < 512; idx += 256) {
        int nt = idx >> 5, ln = idx & 31;
        int n = nt * 8 + (ln >> 2);
        int k0 = (ln & 3) * 2;
        float v0, v1;
        if (k0 < 6) { v0 = __ldg(w1 + k0 * 128 + n); v1 = __ldg(w1 + (k0 + 1) * 128 + n); }
        else        { v0 = __ldg(b1 + n); v1 = 0.f; }
        uint hi, lo;
        split2(v0, v1, hi, lo);
        s_w1f[idx] = make_uint2(hi, lo);
    }
    __syncthreads();

    // ---- W2fT fragments built directly from w2 (BN folded inline) ----
    for (int idx = tid; idx < 4096; idx += 256) {
        int ln = idx & 31;
        int k2 = (idx >> 5) & 3;
        int nt = (idx >> 7) & 15;
        int hl = idx >> 11;
        int n = nt * 8 + (ln >> 2);
        int kg0 = (2 * k2) * 16 + (ln & 3) * 2;
        uint4 v;
#pragma unroll
        for (int q = 0; q < 4; q++) {
            int k = kg0 + q * 8;
            float v0 = s_s[k]     * __ldg(w2 + (size_t)k * 128 + n);
            float v1 = s_s[k + 1] * __ldg(w2 + (size_t)(k + 1) * 128 + n);
            uint hi, lo;
            split2(v0, v1, hi, lo);
            ((uint*)&v)[q] = hl ? lo : hi;
        }
        s_bfrag[idx] = v;
    }
    // ---- b2f computed locally ----
    if (tid < 128) {
        float acc = __ldg(b2 + tid);
#pragma unroll 8
        for (int i = 0; i < 128; i++) acc += s_t[i] * __ldg(w2 + i * 128 + tid);
        s_b2f[tid] = acc;
    }
    __syncthreads();

    int r1 = lane >> 2;
    int cq = (lane & 3) * 2;
    int nT = (E + 15) >> 4;   // 16 edges per warp-iter

    // Rows r1 = half0 of edge ebase+r1, rows r1+8 = half1 of the SAME edge.
    auto build_tile = [&](int ebase, uint Ahi[8][4], uint Alo[8][4]) {
        int e = min(ebase + r1, E - 1);
        uint zhi0, zlo0, zhi1, zlo1;
        if (cq < 6) {
            const float* zp = edgenet + (size_t)e * 12 + cq;
            float2 za = __ldg((const float2*)zp);        // half0 (8B aligned)
            float2 zb = __ldg((const float2*)(zp + 6));  // half1
            split2(za.x, za.y, zhi0, zlo0);
            split2(zb.x, zb.y, zhi1, zlo1);
        } else {
            zhi0 = 0x00003f80u;  // (1.0, 0) bf16x2: bias row selector
            zhi1 = 0x00003f80u;
            zlo0 = 0u; zlo1 = 0u;
        }
#pragma unroll
        for (int j = 0; j < 8; j++) {
            uint2 we = s_w1f[(2 * j) * 32 + lane];
            uint2 wo = s_w1f[(2 * j + 1) * 32 + lane];
            float De[4] = {0.f, 0.f, 0.f, 0.f};
            float Do[4] = {0.f, 0.f, 0.f, 0.f};
            mma16808(De, zhi0, zhi1, we.x);
            mma16816(De, zlo0, zlo1, zhi0, zhi1, we.x, we.y);   // zlo*Whi + zhi*Wlo
            mma16808(Do, zhi0, zhi1, wo.x);
            mma16816(Do, zlo0, zlo1, zhi0, zhi1, wo.x, wo.y);
            float v0 = fmaxf(De[0], 0.f), v1 = fmaxf(De[1], 0.f);
            float v2 = fmaxf(De[2], 0.f), v3 = fmaxf(De[3], 0.f);
            split2(v0, v1, Ahi[j][0], Alo[j][0]);
            split2(v2, v3, Ahi[j][1], Alo[j][1]);
            v0 = fmaxf(Do[0], 0.f); v1 = fmaxf(Do[1], 0.f);
            v2 = fmaxf(Do[2], 0.f); v3 = fmaxf(Do[3], 0.f);
            split2(v0, v1, Ahi[j][2], Alo[j][2]);
            split2(v2, v3, Ahi[j][3], Alo[j][3]);
        }
    };

    for (int t = blockIdx.x * 8 + wid; t < nT; t += gridDim.x * 8) {
        int e0 = t << 4;

        uint Ahi0[8][4], Alo0[8][4], Ahi1[8][4], Alo1[8][4];
        build_tile(e0, Ahi0, Alo0);        // edges e0   .. e0+7
        build_tile(e0 + 8, Ahi1, Alo1);    // edges e0+8 .. e0+15

        float num0 = 0.f, p10 = 0.f, p20 = 0.f;
        float num1 = 0.f, p11 = 0.f, p21 = 0.f;

#pragma unroll 1
        for (int nt = 0; nt < 16; nt++) {
            const uint4* ph = s_bfrag + (nt * 4) * 32 + lane;
            const uint4* pl = ph + 16 * 4 * 32;
            uint4 bh0 = ph[0], bh1 = ph[32], bh2 = ph[64], bh3 = ph[96];
            uint4 bl0 = pl[0], bl1 = pl[32], bl2 = pl[64], bl3 = pl[96];
            uint bh[16] = {bh0.x, bh0.y, bh0.z, bh0.w, bh1.x, bh1.y, bh1.z, bh1.w,
                           bh2.x, bh2.y, bh2.z, bh2.w, bh3.x, bh3.y, bh3.z, bh3.w};
            uint bl[16] = {bl0.x, bl0.y, bl0.z, bl0.w, bl1.x, bl1.y, bl1.z, bl1.w,
                           bl2.x, bl2.y, bl2.z, bl2.w, bl3.x, bl3.y, bl3.z, bl3.w};
            float2 bb = *(const float2*)(s_b2f + nt * 8 + cq);

            {
                float dA0 = 0.f, dA1 = 0.f, dA2 = 0.f, dA3 = 0.f;
                float dB0 = 0.f, dB1 = 0.f, dB2 = 0.f, dB3 = 0.f;
                float dC0 = 0.f, dC1 = 0.f, dC2 = 0.f, dC3 = 0.f;
#pragma unroll
                for (int k = 0; k < 8; k++) {
                    mma16816s(dA0, dA1, dA2, dA3, Ahi0[k][0], Ahi0[k][1], Ahi0[k][2], Ahi0[k][3],
                              bh[2 * k], bh[2 * k + 1]);
                    mma16816s(dB0, dB1, dB2, dB3, Ahi0[k][0], Ahi0[k][1], Ahi0[k][2], Ahi0[k][3],
                              bl[2 * k], bl[2 * k + 1]);
                    mma16816s(dC0, dC1, dC2, dC3, Alo0[k][0], Alo0[k][1], Alo0[k][2], Alo0[k][3],
                              bh[2 * k], bh[2 * k + 1]);
                }
                float o0 = dA0 + dB0 + dC0 + bb.x;
                float o1 = dA1 + dB1 + dC1 + bb.y;
                float o2 = dA2 + dB2 + dC2 + bb.x;
                float o3 = dA3 + dB3 + dC3 + bb.y;
                num0 = fmaf(o0, o2, fmaf(o1, o3, num0));
                p10  = fmaf(o0, o0, fmaf(o1, o1, p10));
                p20  = fmaf(o2, o2, fmaf(o3, o3, p20));
            }
            {
                float dA0 = 0.f, dA1 = 0.f, dA2 = 0.f, dA3 = 0.f;
                float dB0 = 0.f, dB1 = 0.f, dB2 = 0.f, dB3 = 0.f;
                float dC0 = 0.f, dC1 = 0.f, dC2 = 0.f, dC3 = 0.f;
#pragma unroll
                for (int k = 0; k < 8; k++) {
                    mma16816s(dA0, dA1, dA2, dA3, Ahi1[k][0], Ahi1[k][1], Ahi1[k][2], Ahi1[k][3],
                              bh[2 * k], bh[2 * k + 1]);
                    mma16816s(dB0, dB1, dB2, dB3, Ahi1[k][0], Ahi1[k][1], Ahi1[k][2], Ahi1[k][3],
                              bl[2 * k], bl[2 * k + 1]);
                    mma16816s(dC0, dC1, dC2, dC3, Alo1[k][0], Alo1[k][1], Alo1[k][2], Alo1[k][3],
                              bh[2 * k], bh[2 * k + 1]);
                }
                float o0 = dA0 + dB0 + dC0 + bb.x;
                float o1 = dA1 + dB1 + dC1 + bb.y;
                float o2 = dA2 + dB2 + dC2 + bb.x;
                float o3 = dA3 + dB3 + dC3 + bb.y;
                num1 = fmaf(o0, o2, fmaf(o1, o3, num1));
                p11  = fmaf(o0, o0, fmaf(o1, o1, p11));
                p21  = fmaf(o2, o2, fmaf(o3, o3, p21));
            }
        }

#pragma unroll
        for (int off = 1; off <= 2; off <<= 1) {
            num0 += __shfl_xor_sync(0xffffffffu, num0, off);
            p10  += __shfl_xor_sync(0xffffffffu, p10, off);
            p20  += __shfl_xor_sync(0xffffffffu, p20, off);
            num1 += __shfl_xor_sync(0xffffffffu, num1, off);
            p11  += __shfl_xor_sync(0xffffffffu, p11, off);
            p21  += __shfl_xor_sync(0xffffffffu, p21, off);
        }

        if ((lane & 3) == 0) {
            int eA = e0 + r1;
            int eB = e0 + 8 + r1;
            if (eA < E) {
                float den = fmaxf(sqrtf(p10) * sqrtf(p20), 1e-8f);
                float w = fmaf(num0 / den, 0.5f, 0.5f);
                ew[eA] = w;
                atomicAdd(&deg[__ldg(rowidx + eA)], w);
            }
            if (eB < E) {
                float den = fmaxf(sqrtf(p11) * sqrtf(p21), 1e-8f);
                float w = fmaf(num1 / den, 0.5f, 0.5f);
                ew[eB] = w;
                atomicAdd(&deg[__ldg(rowidx + eB)], w);
            }
        }
    }
}

// =================== CSR build ===================
__global__ void hist_kernel(const int* __restrict__ row, int* __restrict__ cnt, int E) {
    int e = blockIdx.x * blockDim.x + threadIdx.x;
    if (e < E) atomicAdd(&cnt[row[e]], 1);
}

__global__ void scan_kernel(const int* __restrict__ cnt, int N,
                            int* __restrict__ rowptr, int* __restrict__ cursor) {
    __shared__ int part[1024];
    int t = threadIdx.x;
    int chunk = (N + 1023) / 1024;
    int b = t * chunk, e = min(b + chunk, N);
    int s = 0;
    for (int i = b; i < e; i++) s += cnt[i];
    part[t] = s;
    __syncthreads();
    for (int off = 1; off < 1024; off <<= 1) {
        int v = (t >= off) ? part[t - off] : 0;
        __syncthreads();
        part[t] += v;
        __syncthreads();
    }
    int run = t ? part[t - 1] : 0;
    for (int i = b; i < e; i++) {
        rowptr[i] = run;
        cursor[i] = run;
        run += cnt[i];
    }
    if (t == 1023) rowptr[N] = run;
}

__global__ void scatter_kernel(const int* __restrict__ row, const int* __restrict__ col,
                               int* __restrict__ cursor, int* __restrict__ ecol,
                               int* __restrict__ eidx, int E) {
    int e = blockIdx.x * blockDim.x + threadIdx.x;
    if (e >= E) return;
    int pos = atomicAdd(&cursor[row[e]], 1);
    ecol[pos] = col[e];
    eidx[pos] = e;
}

// dis[i] = deg>0 ? rsqrt(deg) : 0  (deg accumulated inside PAE)
__global__ void dis_kernel(const float* __restrict__ deg, float* __restrict__ dis, int N) {
    int i = blockIdx.x * blockDim.x + threadIdx.x;
    if (i < N) {
        float d = deg[i];
        dis[i] = (d > 0.f) ? rsqrtf(d) : 0.f;
    }
}

// ewp[i] = {col, ew[eidx[i]] * dis[col]}
__global__ void ewp_kernel(const float* __restrict__ ew, const int* __restrict__ eidx,
                           const int* __restrict__ ecol, const float* __restrict__ dis,
                           uint2* __restrict__ ewp, int E) {
    int i = blockIdx.x * blockDim.x + threadIdx.x;
    if (i >= E) return;
    int c = __ldg(ecol + i);
    float w = __ldg(ew + __ldg(eidx + i)) * __ldg(dis + c);
    ewp[i] = make_uint2((uint)c, __float_as_uint(w));
}

// =================== fused CSR SpMM pass 1: v = u1 + 2*(-dis)*L'(u2) ===================
__global__ __launch_bounds__(256)
void spmm_v(const float* __restrict__ u,
            const int* __restrict__ rowptr, const uint2* __restrict__ ewp,
            const float* __restrict__ dis,
            float* __restrict__ v, int N) {
    int warp = (blockIdx.x * blockDim.x + threadIdx.x) >> 5;
    int lane = threadIdx.x & 31;
    if (warp >= N) return;
    int beg = rowptr[warp], end = rowptr[warp + 1];
    int qe = lane >> 3;      // edge slot 0..3
    int cl = lane & 7;       // col group
    float4 a0 = {0.f, 0.f, 0.f, 0.f};
    float4 a1 = {0.f, 0.f, 0.f, 0.f};
#pragma unroll 2
    for (int i = beg + qe; i < end; i += 4) {
        uint2 p = __ldg(ewp + i);
        float w = __uint_as_float(p.y);
        const float* xp = u + (size_t)p.x * 192 + 128;
        float4 x0 = *(const float4*)(xp + cl * 4);
        float4 x1 = *(const float4*)(xp + 32 + cl * 4);
        a0.x = fmaf(w, x0.x, a0.x); a0.y = fmaf(w, x0.y, a0.y);
        a0.z = fmaf(w, x0.z, a0.z); a0.w = fmaf(w, x0.w, a0.w);
        a1.x = fmaf(w, x1.x, a1.x); a1.y = fmaf(w, x1.y, a1.y);
        a1.z = fmaf(w, x1.z, a1.z); a1.w = fmaf(w, x1.w, a1.w);
    }
#pragma unroll
    for (int off = 16; off >= 8; off >>= 1) {
        a0.x += __shfl_down_sync(0xffffffffu, a0.x, off);
        a0.y += __shfl_down_sync(0xffffffffu, a0.y, off);
        a0.z += __shfl_down_sync(0xffffffffu, a0.z, off);
        a0.w += __shfl_down_sync(0xffffffffu, a0.w, off);
        a1.x += __shfl_down_sync(0xffffffffu, a1.x, off);
        a1.y += __shfl_down_sync(0xffffffffu, a1.y, off);
        a1.z += __shfl_down_sync(0xffffffffu, a1.z, off);
        a1.w += __shfl_down_sync(0xffffffffu, a1.w, off);
    }
    if (lane < 8) {
        float sc = -2.f * __ldg(dis + warp);
        const float* up = u + (size_t)warp * 192 + 64;
        float4 u1a = *(const float4*)(up + cl * 4);
        float4 u1b = *(const float4*)(up + 32 + cl * 4);
        float4 o0, o1;
        o0.x = fmaf(sc, a0.x, u1a.x); o0.y = fmaf(sc, a0.y, u1a.y);
        o0.z = fmaf(sc, a0.z, u1a.z); o0.w = fmaf(sc, a0.w, u1a.w);
        o1.x = fmaf(sc, a1.x, u1b.x); o1.y = fmaf(sc, a1.y, u1b.y);
        o1.z = fmaf(sc, a1.z, u1b.z); o1.w = fmaf(sc, a1.w, u1b.w);
        float* vp = v + (size_t)warp * 64;
        *(float4*)(vp + cl * 4) = o0;
        *(float4*)(vp + 32 + cl * 4) = o1;
    }
}

// =================== fused CSR SpMM pass 2: h = relu(u0 + (-dis)*L'(v)) -> hbuf, jk ===================
__global__ __launch_bounds__(256)
void spmm_h(const float* __restrict__ v, const float* __restrict__ u,
            const int* __restrict__ rowptr, const uint2* __restrict__ ewp,
            const float* __restrict__ dis,
            float* __restrict__ hbuf, float* __restrict__ jk, int N) {
    int warp = (blockIdx.x * blockDim.x + threadIdx.x) >> 5;
    int lane = threadIdx.x & 31;
    if (warp >= N) return;
    int beg = rowptr[warp], end = rowptr[warp + 1];
    int qe = lane >> 3;
    int cl = lane & 7;
    float4 a0 = {0.f, 0.f, 0.f, 0.f};
    float4 a1 = {0.f, 0.f, 0.f, 0.f};
#pragma unroll 2
    for (int i = beg + qe; i < end; i += 4) {
        uint2 p = __ldg(ewp + i);
        float w = __uint_as_float(p.y);
        const float* xp = v + (size_t)p.x * 64;
        float4 x0 = *(const float4*)(xp + cl * 4);
        float4 x1 = *(const float4*)(xp + 32 + cl * 4);
        a0.x = fmaf(w, x0.x, a0.x); a0.y = fmaf(w, x0.y, a0.y);
        a0.z = fmaf(w, x0.z, a0.z); a0.w = fmaf(w, x0.w, a0.w);
        a1.x = fmaf(w, x1.x, a1.x); a1.y = fmaf(w, x1.y, a1.y);
        a1.z = fmaf(w, x1.z, a1.z); a1.w = fmaf(w, x1.w, a1.w);
    }
#pragma unroll
    for (int off = 16; off >= 8; off >>= 1) {
        a0.x += __shfl_down_sync(0xffffffffu, a0.x, off);
        a0.y += __shfl_down_sync(0xffffffffu, a0.y, off);
        a0.z += __shfl_down_sync(0xffffffffu, a0.z, off);
        a0.w += __shfl_down_sync(0xffffffffu, a0.w, off);
        a1.x += __shfl_down_sync(0xffffffffu, a1.x, off);
        a1.y += __shfl_down_sync(0xffffffffu, a1.y, off);
        a1.z += __shfl_down_sync(0xffffffffu, a1.z, off);
        a1.w += __shfl_down_sync(0xffffffffu, a1.w, off);
    }
    if (lane < 8) {
        float sc = -__ldg(dis + warp);
        const float* up = u + (size_t)warp * 192;
        float4 u0a = *(const float4*)(up + cl * 4);
        float4 u0b = *(const float4*)(up + 32 + cl * 4);
        float4 o0, o1;
        o0.x = fmaxf(fmaf(sc, a0.x, u0a.x), 0.f); o0.y = fmaxf(fmaf(sc, a0.y, u0a.y), 0.f);
        o0.z = fmaxf(fmaf(sc, a0.z, u0a.z), 0.f); o0.w = fmaxf(fmaf(sc, a0.w, u0a.w), 0.f);
        o1.x = fmaxf(fmaf(sc, a1.x, u0b.x), 0.f); o1.y = fmaxf(fmaf(sc, a1.y, u0b.y), 0.f);
        o1.z = fmaxf(fmaf(sc, a1.z, u0b.z), 0.f); o1.w = fmaxf(fmaf(sc, a1.w, u0b.w), 0.f);
        float* hp = hbuf + (size_t)warp * 64;
        float* jp = jk + (size_t)warp * 256;
        *(float4*)(hp + cl * 4) = o0;
        *(float4*)(hp + 32 + cl * 4) = o1;
        *(float4*)(jp + cl * 4) = o0;
        *(float4*)(jp + 32 + cl * 4) = o1;
    }
}

// =================== launcher ===================
extern "C" void kernel_launch(void* const* d_in, const int* in_sizes, int n_in,
                              void* d_out, int out_size) {
    const float* features = (const float*)d_in[0];
    const int* edge_index = (const int*)d_in[1];
    const float* edgenet  = (const float*)d_in[2];
    const float* pae_w1 = (const float*)d_in[3];
    const float* pae_b1 = (const float*)d_in[4];
    const float* pae_bn_g = (const float*)d_in[5];
    const float* pae_bn_b = (const float*)d_in[6];
    const float* pae_bn_rm = (const float*)d_in[7];
    const float* pae_bn_rv = (const float*)d_in[8];
    const float* pae_w2 = (const float*)d_in[9];
    const float* pae_b2 = (const float*)d_in[10];
    const float* cheb_w[4] = {(const float*)d_in[11], (const float*)d_in[12],
                              (const float*)d_in[13], (const float*)d_in[14]};
    const float* cls_w1 = (const float*)d_in[15];
    const float* cls_b1 = (const float*)d_in[16];
    const float* cls_bn_g = (const float*)d_in[17];
    const float* cls_bn_b = (const float*)d_in[18];
    const float* cls_bn_rm = (const float*)d_in[19];
    const float* cls_bn_rv = (const float*)d_in[20];
    const float* cls_w2 = (const float*)d_in[21];
    const float* cls_b2 = (const float*)d_in[22];

    int N = in_sizes[0] / 128;
    int E = in_sizes[1] / 2;
    const int* row = edge_index;
    const int* col = edge_index + E;

    float* out = (float*)d_out;
    float* jk = out;
    float* logit = out + (size_t)N * 256;
    float* ew = logit + (size_t)N * 2;

    float *vbuf, *ubuf, *ha, *hb, *dis, *deg, *cw2, *cb2;
    uint2* ewp;
    int *rowptr, *cursor, *cnt, *ecol, *eidx;
    uint4 *frag_cheb[4], *frag_cls;
    cudaGetSymbolAddress((void**)&vbuf, g_v);
    cudaGetSymbolAddress((void**)&ubuf, g_u);
    cudaGetSymbolAddress((void**)&ha, g_ha);
    cudaGetSymbolAddress((void**)&hb, g_hb);
    cudaGetSymbolAddress((void**)&ewp, g_ewp);
    cudaGetSymbolAddress((void**)&dis, g_dis);
    cudaGetSymbolAddress((void**)&deg, g_deg);
    cudaGetSymbolAddress((void**)&rowptr, g_rowptr);
    cudaGetSymbolAddress((void**)&cursor, g_cursor);
    cudaGetSymbolAddress((void**)&cnt, g_cnt);
    cudaGetSymbolAddress((void**)&ecol, g_ecol);
    cudaGetSymbolAddress((void**)&eidx, g_eidx);
    cudaGetSymbolAddress((void**)&cw2, g_cw2);
    cudaGetSymbolAddress((void**)&cb2, g_cb2);
    cudaGetSymbolAddress((void**)&frag_cheb[0], g_frag_cheb0);
    cudaGetSymbolAddress((void**)&frag_cheb[1], g_frag_cheb1);
    cudaGetSymbolAddress((void**)&frag_cheb[2], g_frag_cheb2);
    cudaGetSymbolAddress((void**)&frag_cheb[3], g_frag_cheb3);
    cudaGetSymbolAddress((void**)&frag_cls, g_frag_cls);

    cudaFuncSetAttribute(pae_mma_kernel, cudaFuncAttributeMaxDynamicSharedMemorySize, PAE_SMEM);
    cudaFuncSetAttribute(gemm_mma, cudaFuncAttributeMaxDynamicSharedMemorySize, 65536);
    cudaFuncSetAttribute(gemm_mma3, cudaFuncAttributeMaxDynamicSharedMemorySize, 49152);
    cudaFuncSetAttribute(gemm_mma_cls, cudaFuncAttributeMaxDynamicSharedMemorySize, 65536);

    int rowTiles = (N + 127) / 128;
    int rowWarpBlocks = (N * 32 + 255) / 256;

    // ---- fork: side stream does CSR build + weight prep + layer-0 GEMM ----
    cudaEventRecord(g_evF, 0);
    cudaStreamWaitEvent(g_s2, g_evF, 0);

    cudaMemsetAsync(cnt, 0, (size_t)N * sizeof(int), g_s2);
    hist_kernel<<<(E + 255) / 256, 256, 0, g_s2>>>(row, cnt, E);
    scan_kernel<<<1, 1024, 0, g_s2>>>(cnt, N, rowptr, cursor);
    scatter_kernel<<<(E + 255) / 256, 256, 0, g_s2>>>(row, col, cursor, ecol, eidx, E);
    fold_cls_kernel<<<1, 256, 0, g_s2>>>(cls_bn_g, cls_bn_b, cls_bn_rm, cls_bn_rv,
                                         cls_w2, cls_b2, cw2, cb2);
    prep_cheb_frag128<<<24, 256, 0, g_s2>>>(cheb_w[0], frag_cheb[0]);
    prep_cheb_frag64x3<<<dim3(12, 3), 256, 0, g_s2>>>(cheb_w[1], cheb_w[2], cheb_w[3],
                                                      frag_cheb[1], frag_cheb[2], frag_cheb[3]);
    prep_frag<<<64, 256, 0, g_s2>>>(cls_w1, 256, 256, frag_cls);
    logit_init_kernel<<<(N + 255) / 256, 256, 0, g_s2>>>(cb2, logit, N);
    // layer-0 GEMM is graph-independent: u = features @ [W0-W2 | W1 | W2]
    gemm_mma<<<dim3(rowTiles, 3), 256, 8 * 4096, g_s2>>>(
        features, 128, N, frag_cheb[0], 8, 192, ubuf);

    // ---- main stream: PAE (BN fold inlined; deg accumulated inside) ----
    cudaMemsetAsync(deg, 0, (size_t)N * sizeof(float));
    pae_mma_kernel<<<148, 256, PAE_SMEM>>>(edgenet, pae_w1, pae_b1,
                                           pae_bn_g, pae_bn_b, pae_bn_rm, pae_bn_rv,
                                           pae_w2, pae_b2, row, ew, deg, E);

    // ---- join ----
    cudaEventRecord(g_evJ, g_s2);
    cudaStreamWaitEvent(0, g_evJ, 0);

    // ---- graph normalization ----
    dis_kernel<<<(N + 255) / 256, 256>>>(deg, dis, N);
    ewp_kernel<<<(E + 255) / 256, 256>>>(ew, eidx, ecol, dis, ewp, E);

    // ---- GCN layers (layer 0's GEMM already done on side stream) ----
    float* hbufs[2] = {ha, hb};
    for (int l = 0; l < 4; l++) {
        if (l > 0) {
            gemm_mma3<<<rowTiles, 256, 48 * 1024>>>(
                hbufs[(l - 1) & 1], N, frag_cheb[l], ubuf);
        }
        spmm_v<<<rowWarpBlocks, 256>>>(ubuf, rowptr, ewp, dis, vbuf, N);
        spmm_h<<<rowWarpBlocks, 256>>>(vbuf, ubuf, rowptr, ewp, dis,
                                       hbufs[l & 1], jk + (size_t)l * 64, N);
    }

    // ---- classifier fused with logit ----
    gemm_mma_cls<<<dim3(rowTiles, 4), 256, 16 * 4096>>>(
        jk, 256, N, frag_cls, 16, cls_b1, cw2, logit);
}

// round 15
// speedup vs baseline: 1.0056x; 1.0056x over previous
#include <cuda_runtime.h>
#include <cuda_bf16.h>
#include <math.h>
#include <stdint.h>

typedef unsigned long long ull;
typedef unsigned int uint;

#define NMAX 50000
#define EMAX 1600000

// ---------------- device scratch (no allocations allowed) ----------------
__device__ float g_v[(size_t)NMAX * 64];        // v = u1 + 2*L(u2)
__device__ float g_u[(size_t)NMAX * 192];       // [u0 | u1 | u2]
__device__ float g_ha[(size_t)NMAX * 64];
__device__ float g_hb[(size_t)NMAX * 64];
__device__ uint2 g_ewp[EMAX];                   // {col, ew*dis[col]} in CSR order
__device__ float g_deg[NMAX];
__device__ int   g_rowptr[NMAX + 1];
__device__ int   g_cursor[NMAX];
__device__ int   g_cnt[NMAX];
__device__ int   g_ecol[EMAX];                  // col in CSR order
__device__ int   g_eidx[EMAX];                  // original edge id in CSR order
__device__ __nv_bfloat16 g_w2t_hi[128 * 128];   // PAE W2fT hi, [n][k]
__device__ __nv_bfloat16 g_w2t_lo[128 * 128];   // PAE W2fT lo
__device__ float g_b2f[128];
__device__ float g_cw2[256 * 2];
__device__ float g_cb2[2];
// B fragments for mma GEMMs (uint4 = {hi_b0, hi_b1, lo_b0, lo_b1})
__device__ uint4 g_frag_cheb0[3 * 8 * 256];     // K=128, 192 cols
__device__ uint4 g_frag_cheb1[3 * 4 * 256];     // K=64
__device__ uint4 g_frag_cheb2[3 * 4 * 256];
__device__ uint4 g_frag_cheb3[3 * 4 * 256];
__device__ uint4 g_frag_cls[4 * 16 * 256];      // K=256, 256 cols

// ---------------- side stream + fork/join events (created pre-main, reused) ----------------
static cudaStream_t g_s2 = []() {
    cudaStream_t s; cudaStreamCreateWithFlags(&s, cudaStreamNonBlocking); return s;
}();
static cudaEvent_t g_evF = []() {
    cudaEvent_t e; cudaEventCreateWithFlags(&e, cudaEventDisableTiming); return e;
}();
static cudaEvent_t g_evJ = []() {
    cudaEvent_t e; cudaEventCreateWithFlags(&e, cudaEventDisableTiming); return e;
}();

// =================== warp-level bf16 MMA ===================
__device__ __forceinline__ void mma16816(float* d,
                                         uint a0, uint a1, uint a2, uint a3,
                                         uint b0, uint b1) {
    asm volatile(
        "mma.sync.aligned.m16n8k16.row.col.f32.bf16.bf16.f32 "
        "{%0,%1,%2,%3}, {%4,%5,%6,%7}, {%8,%9}, {%0,%1,%2,%3};"
        : "+f"(d[0]), "+f"(d[1]), "+f"(d[2]), "+f"(d[3])
        : "r"(a0), "r"(a1), "r"(a2), "r"(a3), "r"(b0), "r"(b1));
}

__device__ __forceinline__ void mma16816s(float& d0, float& d1, float& d2, float& d3,
                                          uint a0, uint a1, uint a2, uint a3,
                                          uint b0, uint b1) {
    asm volatile(
        "mma.sync.aligned.m16n8k16.row.col.f32.bf16.bf16.f32 "
        "{%0,%1,%2,%3}, {%4,%5,%6,%7}, {%8,%9}, {%0,%1,%2,%3};"
        : "+f"(d0), "+f"(d1), "+f"(d2), "+f"(d3)
        : "r"(a0), "r"(a1), "r"(a2), "r"(a3), "r"(b0), "r"(b1));
}

__device__ __forceinline__ void mma16808(float* d, uint a0, uint a1, uint b0) {
    asm volatile(
        "mma.sync.aligned.m16n8k8.row.col.f32.bf16.bf16.f32 "
        "{%0,%1,%2,%3}, {%4,%5}, {%6}, {%0,%1,%2,%3};"
        : "+f"(d[0]), "+f"(d[1]), "+f"(d[2]), "+f"(d[3])
        : "r"(a0), "r"(a1), "r"(b0));
}

__device__ __forceinline__ void split2(float a, float b, uint& hi, uint& lo) {
    __nv_bfloat162 h = __floats2bfloat162_rn(a, b);
    float2 f = __bfloat1622float2(h);
    __nv_bfloat162 l = __floats2bfloat162_rn(a - f.x, b - f.y);
    hi = *(uint*)&h;
    lo = *(uint*)&l;
}

// =================== BN folding kernels ===================
__global__ void fold_pae_kernel(const float* __restrict__ g, const float* __restrict__ b,
                                const float* __restrict__ rm, const float* __restrict__ rv,
                                const float* __restrict__ w2, const float* __restrict__ b2,
                                __nv_bfloat16* __restrict__ wt_hi, __nv_bfloat16* __restrict__ wt_lo,
                                float* __restrict__ b2f) {
    int j = threadIdx.x;  // 128 threads
    int blk = blockIdx.x;
    if (blk < 128) {
        float sj = g[j] * rsqrtf(rv[j] + 1e-5f);
        int jj = blk;
        float v = sj * __ldg(w2 + (size_t)j * 128 + jj);
        __nv_bfloat16 hi = __float2bfloat16(v);
        wt_hi[jj * 128 + j] = hi;
        wt_lo[jj * 128 + j] = __float2bfloat16(v - __bfloat162float(hi));
    } else {
        __shared__ float t[128];
        float si = g[j] * rsqrtf(rv[j] + 1e-5f);
        t[j] = b[j] - rm[j] * si;
        __syncthreads();
        float acc = b2[j];
#pragma unroll 8
        for (int i = 0; i < 128; i++) acc += t[i] * __ldg(w2 + i * 128 + j);
        b2f[j] = acc;
    }
}

__global__ void fold_cls_kernel(const float* __restrict__ g, const float* __restrict__ b,
                                const float* __restrict__ rm, const float* __restrict__ rv,
                                const float* __restrict__ w2, const float* __restrict__ b2,
                                float* __restrict__ cw2, float* __restrict__ cb2) {
    __shared__ float p0[256], p1[256];
    int i = threadIdx.x;  // 256 threads
    float si = g[i] * rsqrtf(rv[i] + 1e-5f);
    float ti = b[i] - rm[i] * si;
    float w0 = w2[2 * i], w1 = w2[2 * i + 1];
    cw2[2 * i]     = si * w0;
    cw2[2 * i + 1] = si * w1;
    p0[i] = ti * w0;
    p1[i] = ti * w1;
    __syncthreads();
    for (int off = 128; off; off >>= 1) {
        if (i < off) { p0[i] += p0[i + off]; p1[i] += p1[i + off]; }
        __syncthreads();
    }
    if (i == 0) { cb2[0] = b2[0] + p0[0]; cb2[1] = b2[1] + p1[0]; }
}

__global__ void logit_init_kernel(const float* __restrict__ cb2, float* __restrict__ logit, int N) {
    int i = blockIdx.x * blockDim.x + threadIdx.x;
    if (i < N) {
        logit[2 * i]     = cb2[0];
        logit[2 * i + 1] = cb2[1];
    }
}

// =================== fragment prep kernels ===================
__global__ void prep_frag(const float* __restrict__ W, int K, int Ncols, uint4* __restrict__ out) {
    int ktiles = K >> 4;
    int total = (Ncols >> 6) * ktiles * 256;
    int idx = blockIdx.x * 256 + threadIdx.x;
    if (idx >= total) return;
    int lane = idx & 31;
    int nt = (idx >> 5) & 7;
    int rest = idx >> 8;
    int kt = rest % ktiles;
    int chunk = rest / ktiles;
    int n = chunk * 64 + nt * 8 + (lane >> 2);
    int k0 = kt * 16 + (lane & 3) * 2;
    float w00 = W[(size_t)k0 * Ncols + n];
    float w01 = W[(size_t)(k0 + 1) * Ncols + n];
    float w10 = W[(size_t)(k0 + 8) * Ncols + n];
    float w11 = W[(size_t)(k0 + 9) * Ncols + n];
    uint4 v;
    split2(w00, w01, v.x, v.z);
    split2(w10, w11, v.y, v.w);
    out[idx] = v;
}

// Cheb composite Wc[k][n]: n<64: W0-W2 ; 64<=n<128: W1 ; n>=128: W2.  W: [3][K][64]
__device__ __forceinline__ void cheb_frag_body(const float* __restrict__ W, int K,
                                               uint4* __restrict__ out, int idx) {
    int ktiles = K >> 4;
    int lane = idx & 31;
    int nt = (idx >> 5) & 7;
    int rest = idx >> 8;
    int kt = rest % ktiles;
    int chunk = rest / ktiles;
    int n = chunk * 64 + nt * 8 + (lane >> 2);
    int k0 = kt * 16 + (lane & 3) * 2;
    int part = n >> 6, nn = n & 63;
    float w[4];
#pragma unroll
    for (int q = 0; q < 4; q++) {
        int k = k0 + (q >> 1) * 8 + (q & 1);
        float v;
        if (part == 0)      v = W[(size_t)k * 64 + nn] - W[(size_t)(2 * K + k) * 64 + nn];
        else if (part == 1) v = W[(size_t)(K + k) * 64 + nn];
        else                v = W[(size_t)(2 * K + k) * 64 + nn];
        w[q] = v;
    }
    uint4 v;
    split2(w[0], w[1], v.x, v.z);
    split2(w[2], w[3], v.y, v.w);
    out[idx] = v;
}

__global__ void prep_cheb_frag128(const float* __restrict__ W, uint4* __restrict__ out) {
    int idx = blockIdx.x * 256 + threadIdx.x;
    if (idx < 3 * 8 * 256) cheb_frag_body(W, 128, out, idx);
}

__global__ void prep_cheb_frag64x3(const float* __restrict__ W1, const float* __restrict__ W2,
                                   const float* __restrict__ W3,
                                   uint4* __restrict__ o1, uint4* __restrict__ o2,
                                   uint4* __restrict__ o3) {
    int idx = blockIdx.x * 256 + threadIdx.x;
    if (idx >= 3 * 4 * 256) return;
    const float* W = (blockIdx.y == 0) ? W1 : (blockIdx.y == 1) ? W2 : W3;
    uint4* out = (blockIdx.y == 0) ? o1 : (blockIdx.y == 1) ? o2 : o3;
    cheb_frag_body(W, 64, out, idx);
}

// =================== generic split-bf16 mma GEMM (per-chunk; layer 0) ===================
__global__ __launch_bounds__(256)
void gemm_mma(const float* __restrict__ A, int lda, int M,
              const uint4* __restrict__ bfrag, int ktiles,
              int ldc, float* __restrict__ C) {
    extern __shared__ uint4 sB[];   // [ktiles][8][32]
    int tid = threadIdx.x, lane = tid & 31, wid = tid >> 5;
    const uint4* src = bfrag + (size_t)blockIdx.y * ktiles * 256;
    for (int i = tid; i < ktiles * 256; i += 256) sB[i] = src[i];
    __syncthreads();

    int r1 = blockIdx.x * 128 + wid * 16 + (lane >> 2);
    int r2 = r1 + 8;
    int rl1 = min(r1, M - 1), rl2 = min(r2, M - 1);
    int cq = (lane & 3) * 2;
    const float* A1 = A + (size_t)rl1 * lda;
    const float* A2 = A + (size_t)rl2 * lda;

    float acc[8][4];
#pragma unroll
    for (int i = 0; i < 8; i++) { acc[i][0] = acc[i][1] = acc[i][2] = acc[i][3] = 0.f; }

    for (int kt = 0; kt < ktiles; kt++) {
        int k0 = kt * 16 + cq;
        float2 xa = *(const float2*)(A1 + k0);
        float2 xb = *(const float2*)(A2 + k0);
        float2 xc = *(const float2*)(A1 + k0 + 8);
        float2 xd = *(const float2*)(A2 + k0 + 8);
        uint ahi[4], alo[4];
        split2(xa.x, xa.y, ahi[0], alo[0]);
        split2(xb.x, xb.y, ahi[1], alo[1]);
        split2(xc.x, xc.y, ahi[2], alo[2]);
        split2(xd.x, xd.y, ahi[3], alo[3]);

        const uint4* bp = sB + kt * 256 + lane;
        uint4 b[8];
#pragma unroll
        for (int nt = 0; nt < 8; nt++) b[nt] = bp[nt * 32];
#pragma unroll
        for (int nt = 0; nt < 8; nt++)
            mma16816(acc[nt], ahi[0], ahi[1], ahi[2], ahi[3], b[nt].x, b[nt].y);
#pragma unroll
        for (int nt = 0; nt < 8; nt++)
            mma16816(acc[nt], alo[0], alo[1], alo[2], alo[3], b[nt].x, b[nt].y);
#pragma unroll
        for (int nt = 0; nt < 8; nt++)
            mma16816(acc[nt], ahi[0], ahi[1], ahi[2], ahi[3], b[nt].z, b[nt].w);
    }

#pragma unroll
    for (int nt = 0; nt < 8; nt++) {
        int cc = blockIdx.y * 64 + nt * 8 + cq;
        if (r1 < M) { float2 o = {acc[nt][0], acc[nt][1]}; *(float2*)(C + (size_t)r1 * ldc + cc) = o; }
        if (r2 < M) { float2 o = {acc[nt][2], acc[nt][3]}; *(float2*)(C + (size_t)r2 * ldc + cc) = o; }
    }
}

// =================== merged 3-chunk GEMM for K=64 layers ===================
__global__ __launch_bounds__(256)
void gemm_mma3(const float* __restrict__ A, int M,
               const uint4* __restrict__ bfrag, float* __restrict__ C) {
    extern __shared__ uint4 sB[];   // [3][4][8][32] = 48KB
    int tid = threadIdx.x, lane = tid & 31, wid = tid >> 5;
    for (int i = tid; i < 3 * 4 * 256; i += 256) sB[i] = bfrag[i];
    __syncthreads();

    int r1 = blockIdx.x * 128 + wid * 16 + (lane >> 2);
    int r2 = r1 + 8;
    int rl1 = min(r1, M - 1), rl2 = min(r2, M - 1);
    int cq = (lane & 3) * 2;
    const float* A1 = A + (size_t)rl1 * 64;
    const float* A2 = A + (size_t)rl2 * 64;

    float acc[24][4];
#pragma unroll
    for (int i = 0; i < 24; i++) { acc[i][0] = acc[i][1] = acc[i][2] = acc[i][3] = 0.f; }

#pragma unroll
    for (int kt = 0; kt < 4; kt++) {
        int k0 = kt * 16 + cq;
        float2 xa = *(const float2*)(A1 + k0);
        float2 xb = *(const float2*)(A2 + k0);
        float2 xc = *(const float2*)(A1 + k0 + 8);
        float2 xd = *(const float2*)(A2 + k0 + 8);
        uint ahi[4], alo[4];
        split2(xa.x, xa.y, ahi[0], alo[0]);
        split2(xb.x, xb.y, ahi[1], alo[1]);
        split2(xc.x, xc.y, ahi[2], alo[2]);
        split2(xd.x, xd.y, ahi[3], alo[3]);

#pragma unroll
        for (int c = 0; c < 3; c++) {
            const uint4* bp = sB + (c * 4 + kt) * 256 + lane;
#pragma unroll
            for (int nt = 0; nt < 8; nt++) {
                uint4 b = bp[nt * 32];
                float* d = acc[c * 8 + nt];
                mma16816(d, ahi[0], ahi[1], ahi[2], ahi[3], b.x, b.y);
                mma16816(d, alo[0], alo[1], alo[2], alo[3], b.x, b.y);
                mma16816(d, ahi[0], ahi[1], ahi[2], ahi[3], b.z, b.w);
            }
        }
    }

#pragma unroll
    for (int c = 0; c < 3; c++) {
#pragma unroll
        for (int nt = 0; nt < 8; nt++) {
            int cc = c * 64 + nt * 8 + cq;
            const float* d = acc[c * 8 + nt];
            if (r1 < M) { float2 o = {d[0], d[1]}; *(float2*)(C + (size_t)r1 * 192 + cc) = o; }
            if (r2 < M) { float2 o = {d[2], d[3]}; *(float2*)(C + (size_t)r2 * 192 + cc) = o; }
        }
    }
}

// =================== classifier GEMM fused with logit ===================
__global__ __launch_bounds__(256)
void gemm_mma_cls(const float* __restrict__ A, int lda, int M,
                  const uint4* __restrict__ bfrag, int ktiles,
                  const float* __restrict__ bias, const float* __restrict__ cw2,
                  float* __restrict__ logit) {
    extern __shared__ uint4 sB[];
    int tid = threadIdx.x, lane = tid & 31, wid = tid >> 5;
    const uint4* src = bfrag + (size_t)blockIdx.y * ktiles * 256;
    for (int i = tid; i < ktiles * 256; i += 256) sB[i] = src[i];
    __syncthreads();

    int r1 = blockIdx.x * 128 + wid * 16 + (lane >> 2);
    int r2 = r1 + 8;
    int rl1 = min(r1, M - 1), rl2 = min(r2, M - 1);
    int cq = (lane & 3) * 2;
    const float* A1 = A + (size_t)rl1 * lda;
    const float* A2 = A + (size_t)rl2 * lda;

    float acc[8][4];
#pragma unroll
    for (int i = 0; i < 8; i++) { acc[i][0] = acc[i][1] = acc[i][2] = acc[i][3] = 0.f; }

    for (int kt = 0; kt < ktiles; kt++) {
        int k0 = kt * 16 + cq;
        float2 xa = *(const float2*)(A1 + k0);
        float2 xb = *(const float2*)(A2 + k0);
        float2 xc = *(const float2*)(A1 + k0 + 8);
        float2 xd = *(const float2*)(A2 + k0 + 8);
        uint ahi[4], alo[4];
        split2(xa.x, xa.y, ahi[0], alo[0]);
        split2(xb.x, xb.y, ahi[1], alo[1]);
        split2(xc.x, xc.y, ahi[2], alo[2]);
        split2(xd.x, xd.y, ahi[3], alo[3]);

        const uint4* bp = sB + kt * 256 + lane;
        uint4 b[8];
#pragma unroll
        for (int nt = 0; nt < 8; nt++) b[nt] = bp[nt * 32];
#pragma unroll
        for (int nt = 0; nt < 8; nt++)
            mma16816(acc[nt], ahi[0], ahi[1], ahi[2], ahi[3], b[nt].x, b[nt].y);
#pragma unroll
        for (int nt = 0; nt < 8; nt++)
            mma16816(acc[nt], alo[0], alo[1], alo[2], alo[3], b[nt].x, b[nt].y);
#pragma unroll
        for (int nt = 0; nt < 8; nt++)
            mma16816(acc[nt], ahi[0], ahi[1], ahi[2], ahi[3], b[nt].z, b[nt].w);
    }

    float l0a = 0.f, l1a = 0.f, l0b = 0.f, l1b = 0.f;
#pragma unroll
    for (int nt = 0; nt < 8; nt++) {
        int cc = blockIdx.y * 64 + nt * 8 + cq;
        float b0 = bias[cc], b1 = bias[cc + 1];
        float v0 = fmaxf(acc[nt][0] + b0, 0.f);
        float v1 = fmaxf(acc[nt][1] + b1, 0.f);
        float v2 = fmaxf(acc[nt][2] + b0, 0.f);
        float v3 = fmaxf(acc[nt][3] + b1, 0.f);
        float c00 = cw2[2 * cc], c01 = cw2[2 * cc + 1];
        float c10 = cw2[2 * cc + 2], c11 = cw2[2 * cc + 3];
        l0a = fmaf(v0, c00, fmaf(v1, c10, l0a));
        l1a = fmaf(v0, c01, fmaf(v1, c11, l1a));
        l0b = fmaf(v2, c00, fmaf(v3, c10, l0b));
        l1b = fmaf(v2, c01, fmaf(v3, c11, l1b));
    }
#pragma unroll
    for (int off = 1; off <= 2; off <<= 1) {
        l0a += __shfl_xor_sync(0xffffffffu, l0a, off);
        l1a += __shfl_xor_sync(0xffffffffu, l1a, off);
        l0b += __shfl_xor_sync(0xffffffffu, l0b, off);
        l1b += __shfl_xor_sync(0xffffffffu, l1b, off);
    }
    if ((lane & 3) == 0) {
        if (r1 < M) {
            atomicAdd(&logit[2 * r1], l0a);
            atomicAdd(&logit[2 * r1 + 1], l1a);
        }
        if (r2 < M) {
            atomicAdd(&logit[2 * r2], l0b);
            atomicAdd(&logit[2 * r2 + 1], l1b);
        }
    }
}

// =================== PAE mma.sync kernel (deg accumulation fused into epilogue) ===================
#define PAE_SMEM 70144

__global__ __launch_bounds__(256, 1)
void pae_mma_kernel(const float* __restrict__ edgenet,
                    const float* __restrict__ w1, const float* __restrict__ b1,
                    const __nv_bfloat16* __restrict__ wt_hi, const __nv_bfloat16* __restrict__ wt_lo,
                    const float* __restrict__ b2f, const int* __restrict__ rowidx,
                    float* __restrict__ ew, float* __restrict__ deg, int E) {
    extern __shared__ char smraw[];
    uint4* s_bfrag = (uint4*)smraw;
    uint2* s_w1f = (uint2*)(smraw + 65536);   // [16 ntiles][32 lanes]
    float* s_b2f = (float*)(smraw + 69632);

    int tid = threadIdx.x, lane = tid & 31, wid = tid >> 5;

    if (tid < 128) s_b2f[tid] = b2f[tid];
    for (int idx = tid; idx < 512; idx += 256) {
        int nt = idx >> 5, ln = idx & 31;
        int n = nt * 8 + (ln >> 2);
        int k0 = (ln & 3) * 2;
        float v0, v1;
        if (k0 < 6) { v0 = __ldg(w1 + k0 * 128 + n); v1 = __ldg(w1 + (k0 + 1) * 128 + n); }
        else        { v0 = __ldg(b1 + n); v1 = 0.f; }
        uint hi, lo;
        split2(v0, v1, hi, lo);
        s_w1f[idx] = make_uint2(hi, lo);
    }
    for (int idx = tid; idx < 4096; idx += 256) {
        int ln = idx & 31;
        int k2 = (idx >> 5) & 3;
        int nt = (idx >> 7) & 15;
        int hl = idx >> 11;
        const __nv_bfloat16* src = hl ? wt_lo : wt_hi;
        int n = nt * 8 + (ln >> 2);
        int kg0 = (2 * k2) * 16 + (ln & 3) * 2;
        const __nv_bfloat16* base = src + n * 128;
        uint4 v;
        v.x = *(const uint*)(base + kg0);
        v.y = *(const uint*)(base + kg0 + 8);
        v.z = *(const uint*)(base + kg0 + 16);
        v.w = *(const uint*)(base + kg0 + 24);
        s_bfrag[idx] = v;
    }
    __syncthreads();

    int r1 = lane >> 2;
    int cq = (lane & 3) * 2;
    int nT = (E + 15) >> 4;   // 16 edges per warp-iter

    // Rows r1 = half0 of edge ebase+r1, rows r1+8 = half1 of the SAME edge.
    auto build_tile = [&](int ebase, uint Ahi[8][4], uint Alo[8][4]) {
        int e = min(ebase + r1, E - 1);
        uint zhi0, zlo0, zhi1, zlo1;
        if (cq < 6) {
            const float* zp = edgenet + (size_t)e * 12 + cq;
            float2 za = __ldg((const float2*)zp);        // half0 (8B aligned)
            float2 zb = __ldg((const float2*)(zp + 6));  // half1
            split2(za.x, za.y, zhi0, zlo0);
            split2(zb.x, zb.y, zhi1, zlo1);
        } else {
            zhi0 = 0x00003f80u;  // (1.0, 0) bf16x2: bias row selector
            zhi1 = 0x00003f80u;
            zlo0 = 0u; zlo1 = 0u;
        }
#pragma unroll
        for (int j = 0; j < 8; j++) {
            uint2 we = s_w1f[(2 * j) * 32 + lane];
            uint2 wo = s_w1f[(2 * j + 1) * 32 + lane];
            float De[4] = {0.f, 0.f, 0.f, 0.f};
            float Do[4] = {0.f, 0.f, 0.f, 0.f};
            mma16808(De, zhi0, zhi1, we.x);
            mma16816(De, zlo0, zlo1, zhi0, zhi1, we.x, we.y);   // zlo*Whi + zhi*Wlo
            mma16808(Do, zhi0, zhi1, wo.x);
            mma16816(Do, zlo0, zlo1, zhi0, zhi1, wo.x, wo.y);
            float v0 = fmaxf(De[0], 0.f), v1 = fmaxf(De[1], 0.f);
            float v2 = fmaxf(De[2], 0.f), v3 = fmaxf(De[3], 0.f);
            split2(v0, v1, Ahi[j][0], Alo[j][0]);
            split2(v2, v3, Ahi[j][1], Alo[j][1]);
            v0 = fmaxf(Do[0], 0.f); v1 = fmaxf(Do[1], 0.f);
            v2 = fmaxf(Do[2], 0.f); v3 = fmaxf(Do[3], 0.f);
            split2(v0, v1, Ahi[j][2], Alo[j][2]);
            split2(v2, v3, Ahi[j][3], Alo[j][3]);
        }
    };

    for (int t = blockIdx.x * 8 + wid; t < nT; t += gridDim.x * 8) {
        int e0 = t << 4;

        uint Ahi0[8][4], Alo0[8][4], Ahi1[8][4], Alo1[8][4];
        build_tile(e0, Ahi0, Alo0);        // edges e0   .. e0+7
        build_tile(e0 + 8, Ahi1, Alo1);    // edges e0+8 .. e0+15

        float num0 = 0.f, p10 = 0.f, p20 = 0.f;
        float num1 = 0.f, p11 = 0.f, p21 = 0.f;

#pragma unroll 1
        for (int nt = 0; nt < 16; nt++) {
            const uint4* ph = s_bfrag + (nt * 4) * 32 + lane;
            const uint4* pl = ph + 16 * 4 * 32;
            uint4 bh0 = ph[0], bh1 = ph[32], bh2 = ph[64], bh3 = ph[96];
            uint4 bl0 = pl[0], bl1 = pl[32], bl2 = pl[64], bl3 = pl[96];
            uint bh[16] = {bh0.x, bh0.y, bh0.z, bh0.w, bh1.x, bh1.y, bh1.z, bh1.w,
                           bh2.x, bh2.y, bh2.z, bh2.w, bh3.x, bh3.y, bh3.z, bh3.w};
            uint bl[16] = {bl0.x, bl0.y, bl0.z, bl0.w, bl1.x, bl1.y, bl1.z, bl1.w,
                           bl2.x, bl2.y, bl2.z, bl2.w, bl3.x, bl3.y, bl3.z, bl3.w};
            float2 bb = *(const float2*)(s_b2f + nt * 8 + cq);

            {
                float dA0 = 0.f, dA1 = 0.f, dA2 = 0.f, dA3 = 0.f;
                float dB0 = 0.f, dB1 = 0.f, dB2 = 0.f, dB3 = 0.f;
                float dC0 = 0.f, dC1 = 0.f, dC2 = 0.f, dC3 = 0.f;
#pragma unroll
                for (int k = 0; k < 8; k++) {
                    mma16816s(dA0, dA1, dA2, dA3, Ahi0[k][0], Ahi0[k][1], Ahi0[k][2], Ahi0[k][3],
                              bh[2 * k], bh[2 * k + 1]);
                    mma16816s(dB0, dB1, dB2, dB3, Ahi0[k][0], Ahi0[k][1], Ahi0[k][2], Ahi0[k][3],
                              bl[2 * k], bl[2 * k + 1]);
                    mma16816s(dC0, dC1, dC2, dC3, Alo0[k][0], Alo0[k][1], Alo0[k][2], Alo0[k][3],
                              bh[2 * k], bh[2 * k + 1]);
                }
                float o0 = dA0 + dB0 + dC0 + bb.x;
                float o1 = dA1 + dB1 + dC1 + bb.y;
                float o2 = dA2 + dB2 + dC2 + bb.x;
                float o3 = dA3 + dB3 + dC3 + bb.y;
                num0 = fmaf(o0, o2, fmaf(o1, o3, num0));
                p10  = fmaf(o0, o0, fmaf(o1, o1, p10));
                p20  = fmaf(o2, o2, fmaf(o3, o3, p20));
            }
            {
                float dA0 = 0.f, dA1 = 0.f, dA2 = 0.f, dA3 = 0.f;
                float dB0 = 0.f, dB1 = 0.f, dB2 = 0.f, dB3 = 0.f;
                float dC0 = 0.f, dC1 = 0.f, dC2 = 0.f, dC3 = 0.f;
#pragma unroll
                for (int k = 0; k < 8; k++) {
                    mma16816s(dA0, dA1, dA2, dA3, Ahi1[k][0], Ahi1[k][1], Ahi1[k][2], Ahi1[k][3],
                              bh[2 * k], bh[2 * k + 1]);
                    mma16816s(dB0, dB1, dB2, dB3, Ahi1[k][0], Ahi1[k][1], Ahi1[k][2], Ahi1[k][3],
                              bl[2 * k], bl[2 * k + 1]);
                    mma16816s(dC0, dC1, dC2, dC3, Alo1[k][0], Alo1[k][1], Alo1[k][2], Alo1[k][3],
                              bh[2 * k], bh[2 * k + 1]);
                }
                float o0 = dA0 + dB0 + dC0 + bb.x;
                float o1 = dA1 + dB1 + dC1 + bb.y;
                float o2 = dA2 + dB2 + dC2 + bb.x;
                float o3 = dA3 + dB3 + dC3 + bb.y;
                num1 = fmaf(o0, o2, fmaf(o1, o3, num1));
                p11  = fmaf(o0, o0, fmaf(o1, o1, p11));
                p21  = fmaf(o2, o2, fmaf(o3, o3, p21));
            }
        }

#pragma unroll
        for (int off = 1; off <= 2; off <<= 1) {
            num0 += __shfl_xor_sync(0xffffffffu, num0, off);
            p10  += __shfl_xor_sync(0xffffffffu, p10, off);
            p20  += __shfl_xor_sync(0xffffffffu, p20, off);
            num1 += __shfl_xor_sync(0xffffffffu, num1, off);
            p11  += __shfl_xor_sync(0xffffffffu, p11, off);
            p21  += __shfl_xor_sync(0xffffffffu, p21, off);
        }

        if ((lane & 3) == 0) {
            int eA = e0 + r1;
            int eB = e0 + 8 + r1;
            if (eA < E) {
                float den = fmaxf(sqrtf(p10) * sqrtf(p20), 1e-8f);
                float w = fmaf(num0 / den, 0.5f, 0.5f);
                ew[eA] = w;
                atomicAdd(&deg[__ldg(rowidx + eA)], w);
            }
            if (eB < E) {
                float den = fmaxf(sqrtf(p11) * sqrtf(p21), 1e-8f);
                float w = fmaf(num1 / den, 0.5f, 0.5f);
                ew[eB] = w;
                atomicAdd(&deg[__ldg(rowidx + eB)], w);
            }
        }
    }
}

// =================== CSR build ===================
__global__ void hist_kernel(const int* __restrict__ row, int* __restrict__ cnt, int E) {
    int e = blockIdx.x * blockDim.x + threadIdx.x;
    if (e < E) atomicAdd(&cnt[row[e]], 1);
}

__global__ void scan_kernel(const int* __restrict__ cnt, int N,
                            int* __restrict__ rowptr, int* __restrict__ cursor) {
    __shared__ int part[1024];
    int t = threadIdx.x;
    int chunk = (N + 1023) / 1024;
    int b = t * chunk, e = min(b + chunk, N);
    int s = 0;
    for (int i = b; i < e; i++) s += cnt[i];
    part[t] = s;
    __syncthreads();
    for (int off = 1; off < 1024; off <<= 1) {
        int v = (t >= off) ? part[t - off] : 0;
        __syncthreads();
        part[t] += v;
        __syncthreads();
    }
    int run = t ? part[t - 1] : 0;
    for (int i = b; i < e; i++) {
        rowptr[i] = run;
        cursor[i] = run;
        run += cnt[i];
    }
    if (t == 1023) rowptr[N] = run;
}

__global__ void scatter_kernel(const int* __restrict__ row, const int* __restrict__ col,
                               int* __restrict__ cursor, int* __restrict__ ecol,
                               int* __restrict__ eidx, int E) {
    int e = blockIdx.x * blockDim.x + threadIdx.x;
    if (e >= E) return;
    int pos = atomicAdd(&cursor[row[e]], 1);
    ecol[pos] = col[e];
    eidx[pos] = e;
}

// ewp[i] = {col, ew[eidx[i]] * rsqrt(deg[col])}  (dis folded in)
__global__ void ewp_kernel(const float* __restrict__ ew, const int* __restrict__ eidx,
                           const int* __restrict__ ecol, const float* __restrict__ deg,
                           uint2* __restrict__ ewp, int E) {
    int i = blockIdx.x * blockDim.x + threadIdx.x;
    if (i >= E) return;
    int c = __ldg(ecol + i);
    float d = __ldg(deg + c);
    float ds = (d > 0.f) ? rsqrtf(d) : 0.f;
    float w = __ldg(ew + __ldg(eidx + i)) * ds;
    ewp[i] = make_uint2((uint)c, __float_as_uint(w));
}

// =================== fused CSR SpMM pass 1: v = u1 + 2*(-dis)*L'(u2) ===================
__global__ __launch_bounds__(256)
void spmm_v(const float* __restrict__ u,
            const int* __restrict__ rowptr, const uint2* __restrict__ ewp,
            const float* __restrict__ deg,
            float* __restrict__ v, int N) {
    int warp = (blockIdx.x * blockDim.x + threadIdx.x) >> 5;
    int lane = threadIdx.x & 31;
    if (warp >= N) return;
    int beg = rowptr[warp], end = rowptr[warp + 1];
    int qe = lane >> 3;      // edge slot 0..3
    int cl = lane & 7;       // col group
    float4 a0 = {0.f, 0.f, 0.f, 0.f};
    float4 a1 = {0.f, 0.f, 0.f, 0.f};
#pragma unroll 2
    for (int i = beg + qe; i < end; i += 4) {
        uint2 p = __ldg(ewp + i);
        float w = __uint_as_float(p.y);
        const float* xp = u + (size_t)p.x * 192 + 128;
        float4 x0 = *(const float4*)(xp + cl * 4);
        float4 x1 = *(const float4*)(xp + 32 + cl * 4);
        a0.x = fmaf(w, x0.x, a0.x); a0.y = fmaf(w, x0.y, a0.y);
        a0.z = fmaf(w, x0.z, a0.z); a0.w = fmaf(w, x0.w, a0.w);
        a1.x = fmaf(w, x1.x, a1.x); a1.y = fmaf(w, x1.y, a1.y);
        a1.z = fmaf(w, x1.z, a1.z); a1.w = fmaf(w, x1.w, a1.w);
    }
#pragma unroll
    for (int off = 16; off >= 8; off >>= 1) {
        a0.x += __shfl_down_sync(0xffffffffu, a0.x, off);
        a0.y += __shfl_down_sync(0xffffffffu, a0.y, off);
        a0.z += __shfl_down_sync(0xffffffffu, a0.z, off);
        a0.w += __shfl_down_sync(0xffffffffu, a0.w, off);
        a1.x += __shfl_down_sync(0xffffffffu, a1.x, off);
        a1.y += __shfl_down_sync(0xffffffffu, a1.y, off);
        a1.z += __shfl_down_sync(0xffffffffu, a1.z, off);
        a1.w += __shfl_down_sync(0xffffffffu, a1.w, off);
    }
    if (lane < 8) {
        float d = __ldg(deg + warp);
        float ds = (d > 0.f) ? rsqrtf(d) : 0.f;
        float sc = -2.f * ds;
        const float* up = u + (size_t)warp * 192 + 64;
        float4 u1a = *(const float4*)(up + cl * 4);
        float4 u1b = *(const float4*)(up + 32 + cl * 4);
        float4 o0, o1;
        o0.x = fmaf(sc, a0.x, u1a.x); o0.y = fmaf(sc, a0.y, u1a.y);
        o0.z = fmaf(sc, a0.z, u1a.z); o0.w = fmaf(sc, a0.w, u1a.w);
        o1.x = fmaf(sc, a1.x, u1b.x); o1.y = fmaf(sc, a1.y, u1b.y);
        o1.z = fmaf(sc, a1.z, u1b.z); o1.w = fmaf(sc, a1.w, u1b.w);
        float* vp = v + (size_t)warp * 64;
        *(float4*)(vp + cl * 4) = o0;
        *(float4*)(vp + 32 + cl * 4) = o1;
    }
}

// =================== fused CSR SpMM pass 2: h = relu(u0 + (-dis)*L'(v)) -> hbuf, jk ===================
__global__ __launch_bounds__(256)
void spmm_h(const float* __restrict__ v, const float* __restrict__ u,
            const int* __restrict__ rowptr, const uint2* __restrict__ ewp,
            const float* __restrict__ deg,
            float* __restrict__ hbuf, float* __restrict__ jk, int N) {
    int warp = (blockIdx.x * blockDim.x + threadIdx.x) >> 5;
    int lane = threadIdx.x & 31;
    if (warp >= N) return;
    int beg = rowptr[warp], end = rowptr[warp + 1];
    int qe = lane >> 3;
    int cl = lane & 7;
    float4 a0 = {0.f, 0.f, 0.f, 0.f};
    float4 a1 = {0.f, 0.f, 0.f, 0.f};
#pragma unroll 2
    for (int i = beg + qe; i < end; i += 4) {
        uint2 p = __ldg(ewp + i);
        float w = __uint_as_float(p.y);
        const float* xp = v + (size_t)p.x * 64;
        float4 x0 = *(const float4*)(xp + cl * 4);
        float4 x1 = *(const float4*)(xp + 32 + cl * 4);
        a0.x = fmaf(w, x0.x, a0.x); a0.y = fmaf(w, x0.y, a0.y);
        a0.z = fmaf(w, x0.z, a0.z); a0.w = fmaf(w, x0.w, a0.w);
        a1.x = fmaf(w, x1.x, a1.x); a1.y = fmaf(w, x1.y, a1.y);
        a1.z = fmaf(w, x1.z, a1.z); a1.w = fmaf(w, x1.w, a1.w);
    }
#pragma unroll
    for (int off = 16; off >= 8; off >>= 1) {
        a0.x += __shfl_down_sync(0xffffffffu, a0.x, off);
        a0.y += __shfl_down_sync(0xffffffffu, a0.y, off);
        a0.z += __shfl_down_sync(0xffffffffu, a0.z, off);
        a0.w += __shfl_down_sync(0xffffffffu, a0.w, off);
        a1.x += __shfl_down_sync(0xffffffffu, a1.x, off);
        a1.y += __shfl_down_sync(0xffffffffu, a1.y, off);
        a1.z += __shfl_down_sync(0xffffffffu, a1.z, off);
        a1.w += __shfl_down_sync(0xffffffffu, a1.w, off);
    }
    if (lane < 8) {
        float d = __ldg(deg + warp);
        float sc = (d > 0.f) ? -rsqrtf(d) : 0.f;
        const float* up = u + (size_t)warp * 192;
        float4 u0a = *(const float4*)(up + cl * 4);
        float4 u0b = *(const float4*)(up + 32 + cl * 4);
        float4 o0, o1;
        o0.x = fmaxf(fmaf(sc, a0.x, u0a.x), 0.f); o0.y = fmaxf(fmaf(sc, a0.y, u0a.y), 0.f);
        o0.z = fmaxf(fmaf(sc, a0.z, u0a.z), 0.f); o0.w = fmaxf(fmaf(sc, a0.w, u0a.w), 0.f);
        o1.x = fmaxf(fmaf(sc, a1.x, u0b.x), 0.f); o1.y = fmaxf(fmaf(sc, a1.y, u0b.y), 0.f);
        o1.z = fmaxf(fmaf(sc, a1.z, u0b.z), 0.f); o1.w = fmaxf(fmaf(sc, a1.w, u0b.w), 0.f);
        float* hp = hbuf + (size_t)warp * 64;
        float* jp = jk + (size_t)warp * 256;
        *(float4*)(hp + cl * 4) = o0;
        *(float4*)(hp + 32 + cl * 4) = o1;
        *(float4*)(jp + cl * 4) = o0;
        *(float4*)(jp + 32 + cl * 4) = o1;
    }
}

// =================== launcher ===================
extern "C" void kernel_launch(void* const* d_in, const int* in_sizes, int n_in,
                              void* d_out, int out_size) {
    const float* features = (const float*)d_in[0];
    const int* edge_index = (const int*)d_in[1];
    const float* edgenet  = (const float*)d_in[2];
    const float* pae_w1 = (const float*)d_in[3];
    const float* pae_b1 = (const float*)d_in[4];
    const float* pae_bn_g = (const float*)d_in[5];
    const float* pae_bn_b = (const float*)d_in[6];
    const float* pae_bn_rm = (const float*)d_in[7];
    const float* pae_bn_rv = (const float*)d_in[8];
    const float* pae_w2 = (const float*)d_in[9];
    const float* pae_b2 = (const float*)d_in[10];
    const float* cheb_w[4] = {(const float*)d_in[11], (const float*)d_in[12],
                              (const float*)d_in[13], (const float*)d_in[14]};
    const float* cls_w1 = (const float*)d_in[15];
    const float* cls_b1 = (const float*)d_in[16];
    const float* cls_bn_g = (const float*)d_in[17];
    const float* cls_bn_b = (const float*)d_in[18];
    const float* cls_bn_rm = (const float*)d_in[19];
    const float* cls_bn_rv = (const float*)d_in[20];
    const float* cls_w2 = (const float*)d_in[21];
    const float* cls_b2 = (const float*)d_in[22];

    int N = in_sizes[0] / 128;
    int E = in_sizes[1] / 2;
    const int* row = edge_index;
    const int* col = edge_index + E;

    float* out = (float*)d_out;
    float* jk = out;
    float* logit = out + (size_t)N * 256;
    float* ew = logit + (size_t)N * 2;

    float *vbuf, *ubuf, *ha, *hb, *deg, *b2f, *cw2, *cb2;
    uint2* ewp;
    int *rowptr, *cursor, *cnt, *ecol, *eidx;
    __nv_bfloat16 *wt_hi, *wt_lo;
    uint4 *frag_cheb[4], *frag_cls;
    cudaGetSymbolAddress((void**)&vbuf, g_v);
    cudaGetSymbolAddress((void**)&ubuf, g_u);
    cudaGetSymbolAddress((void**)&ha, g_ha);
    cudaGetSymbolAddress((void**)&hb, g_hb);
    cudaGetSymbolAddress((void**)&ewp, g_ewp);
    cudaGetSymbolAddress((void**)&deg, g_deg);
    cudaGetSymbolAddress((void**)&rowptr, g_rowptr);
    cudaGetSymbolAddress((void**)&cursor, g_cursor);
    cudaGetSymbolAddress((void**)&cnt, g_cnt);
    cudaGetSymbolAddress((void**)&ecol, g_ecol);
    cudaGetSymbolAddress((void**)&eidx, g_eidx);
    cudaGetSymbolAddress((void**)&wt_hi, g_w2t_hi);
    cudaGetSymbolAddress((void**)&wt_lo, g_w2t_lo);
    cudaGetSymbolAddress((void**)&b2f, g_b2f);
    cudaGetSymbolAddress((void**)&cw2, g_cw2);
    cudaGetSymbolAddress((void**)&cb2, g_cb2);
    cudaGetSymbolAddress((void**)&frag_cheb[0], g_frag_cheb0);
    cudaGetSymbolAddress((void**)&frag_cheb[1], g_frag_cheb1);
    cudaGetSymbolAddress((void**)&frag_cheb[2], g_frag_cheb2);
    cudaGetSymbolAddress((void**)&frag_cheb[3], g_frag_cheb3);
    cudaGetSymbolAddress((void**)&frag_cls, g_frag_cls);

    cudaFuncSetAttribute(pae_mma_kernel, cudaFuncAttributeMaxDynamicSharedMemorySize, PAE_SMEM);
    cudaFuncSetAttribute(gemm_mma, cudaFuncAttributeMaxDynamicSharedMemorySize, 65536);
    cudaFuncSetAttribute(gemm_mma3, cudaFuncAttributeMaxDynamicSharedMemorySize, 49152);
    cudaFuncSetAttribute(gemm_mma_cls, cudaFuncAttributeMaxDynamicSharedMemorySize, 65536);

    int rowTiles = (N + 127) / 128;
    int rowWarpBlocks = (N * 32 + 255) / 256;

    // ---- fork: side stream does CSR build + weight prep + layer-0 GEMM ----
    cudaEventRecord(g_evF, 0);
    cudaStreamWaitEvent(g_s2, g_evF, 0);

    cudaMemsetAsync(cnt, 0, (size_t)N * sizeof(int), g_s2);
    hist_kernel<<<(E + 255) / 256, 256, 0, g_s2>>>(row, cnt, E);
    scan_kernel<<<1, 1024, 0, g_s2>>>(cnt, N, rowptr, cursor);
    scatter_kernel<<<(E + 255) / 256, 256, 0, g_s2>>>(row, col, cursor, ecol, eidx, E);
    fold_cls_kernel<<<1, 256, 0, g_s2>>>(cls_bn_g, cls_bn_b, cls_bn_rm, cls_bn_rv,
                                         cls_w2, cls_b2, cw2, cb2);
    prep_cheb_frag128<<<24, 256, 0, g_s2>>>(cheb_w[0], frag_cheb[0]);
    prep_cheb_frag64x3<<<dim3(12, 3), 256, 0, g_s2>>>(cheb_w[1], cheb_w[2], cheb_w[3],
                                                      frag_cheb[1], frag_cheb[2], frag_cheb[3]);
    prep_frag<<<64, 256, 0, g_s2>>>(cls_w1, 256, 256, frag_cls);
    logit_init_kernel<<<(N + 255) / 256, 256, 0, g_s2>>>(cb2, logit, N);
    // layer-0 GEMM is graph-independent: u = features @ [W0-W2 | W1 | W2]
    gemm_mma<<<dim3(rowTiles, 3), 256, 8 * 4096, g_s2>>>(
        features, 128, N, frag_cheb[0], 8, 192, ubuf);

    // ---- main stream: PAE (deg accumulated inside) ----
    cudaMemsetAsync(deg, 0, (size_t)N * sizeof(float));
    fold_pae_kernel<<<129, 128>>>(pae_bn_g, pae_bn_b, pae_bn_rm, pae_bn_rv, pae_w2, pae_b2,
                                  wt_hi, wt_lo, b2f);
    pae_mma_kernel<<<148, 256, PAE_SMEM>>>(edgenet, pae_w1, pae_b1, wt_hi, wt_lo, b2f,
                                           row, ew, deg, E);

    // ---- join ----
    cudaEventRecord(g_evJ, g_s2);
    cudaStreamWaitEvent(0, g_evJ, 0);

    // ---- graph normalization (dis folded into ewp + spmm) ----
    ewp_kernel<<<(E + 255) / 256, 256>>>(ew, eidx, ecol, deg, ewp, E);

    // ---- GCN layers (layer 0's GEMM already done on side stream) ----
    float* hbufs[2] = {ha, hb};
    for (int l = 0; l < 4; l++) {
        if (l > 0) {
            gemm_mma3<<<rowTiles, 256, 48 * 1024>>>(
                hbufs[(l - 1) & 1], N, frag_cheb[l], ubuf);
        }
        spmm_v<<<rowWarpBlocks, 256>>>(ubuf, rowptr, ewp, deg, vbuf, N);
        spmm_h<<<rowWarpBlocks, 256>>>(vbuf, ubuf, rowptr, ewp, deg,
                                       hbufs[l & 1], jk + (size_t)l * 64, N);
    }

    // ---- classifier fused with logit ----
    gemm_mma_cls<<<dim3(rowTiles, 4), 256, 16 * 4096>>>(
        jk, 256, N, frag_cls, 16, cls_b1, cw2, logit);
}